// round 3
// baseline (speedup 1.0000x reference)
#include <cuda_runtime.h>
#include <math.h>

// Problem constants (shapes are fixed by the reference generator)
#define NNODES 500000
#define FIN 16
#define HID 8
#define NCLS 2

// Scratch (device globals; no allocation allowed)
__device__ float g_deg [NNODES];          // degree (float, includes self-loop)
__device__ float g_dinv[NNODES];          // deg^{-1/2}
__device__ float g_p1  [NNODES * HID];    // (x@W1) * dinv  per node
__device__ float g_agg1[NNODES * HID];    // scatter target, layer 1
__device__ float g_p2  [NNODES * NCLS];   // (h@W2) * dinv  per node
__device__ float g_agg2[NNODES * NCLS];   // scatter target, layer 2

// ---------------------------------------------------------------------------
// Vector reductions (sm_90+): one instruction per 16B / 8B of atomic traffic.
// ---------------------------------------------------------------------------
__device__ __forceinline__ void red_add_v4(float* p, float4 v) {
    asm volatile("red.global.add.v4.f32 [%0], {%1,%2,%3,%4};"
                 :: "l"(p), "f"(v.x), "f"(v.y), "f"(v.z), "f"(v.w) : "memory");
}
__device__ __forceinline__ void red_add_v2(float* p, float a, float b) {
    asm volatile("red.global.add.v2.f32 [%0], {%1,%2};"
                 :: "l"(p), "f"(a), "f"(b) : "memory");
}

// ---------------------------------------------------------------------------
// K0: init — deg=1 (self loop), zero both scatter targets
// ---------------------------------------------------------------------------
__global__ void k_init(int n) {
    int i = blockIdx.x * blockDim.x + threadIdx.x;
    if (i >= n) return;
    g_deg[i] = 1.0f;
    float4 z4 = make_float4(0.f, 0.f, 0.f, 0.f);
    ((float4*)(g_agg1 + (size_t)i * HID))[0] = z4;
    ((float4*)(g_agg1 + (size_t)i * HID))[1] = z4;
    ((float2*)(g_agg2 + (size_t)i * NCLS))[0] = make_float2(0.f, 0.f);
}

// ---------------------------------------------------------------------------
// K1: degree — deg[col] += 1 per edge
// ---------------------------------------------------------------------------
__global__ void k_degree(const int* __restrict__ col, int e) {
    int t = blockIdx.x * blockDim.x + threadIdx.x;
    if (t >= e) return;
    atomicAdd(&g_deg[col[t]], 1.0f);
}

// ---------------------------------------------------------------------------
// K2: per-node — dinv = rsqrt(deg); p1 = (x @ W1) * dinv
// ---------------------------------------------------------------------------
__global__ void k_p1(const float* __restrict__ x,
                     const float* __restrict__ W1, int n) {
    __shared__ float sW1[FIN * HID];
    for (int k = threadIdx.x; k < FIN * HID; k += blockDim.x)
        sW1[k] = W1[k];
    __syncthreads();

    int i = blockIdx.x * blockDim.x + threadIdx.x;
    if (i >= n) return;

    const float4* xr = (const float4*)(x + (size_t)i * FIN);
    float xv[FIN];
    #pragma unroll
    for (int q = 0; q < 4; q++) {
        float4 v = xr[q];
        xv[q*4+0] = v.x; xv[q*4+1] = v.y; xv[q*4+2] = v.z; xv[q*4+3] = v.w;
    }
    float h[HID];
    #pragma unroll
    for (int j = 0; j < HID; j++) h[j] = 0.f;
    #pragma unroll
    for (int k = 0; k < FIN; k++) {
        float xk = xv[k];
        #pragma unroll
        for (int j = 0; j < HID; j++) h[j] = fmaf(xk, sW1[k*HID + j], h[j]);
    }
    float d = rsqrtf(g_deg[i]);
    g_dinv[i] = d;
    float4 o0 = make_float4(h[0]*d, h[1]*d, h[2]*d, h[3]*d);
    float4 o1 = make_float4(h[4]*d, h[5]*d, h[6]*d, h[7]*d);
    ((float4*)(g_p1 + (size_t)i * HID))[0] = o0;
    ((float4*)(g_p1 + (size_t)i * HID))[1] = o1;
}

// ---------------------------------------------------------------------------
// K3: edge scatter, layer 1 — agg1[col] += p1[row]  (two v4 REDs / edge)
// ---------------------------------------------------------------------------
__global__ void k_scatter1(const int* __restrict__ row,
                           const int* __restrict__ col, int e) {
    int t = blockIdx.x * blockDim.x + threadIdx.x;
    if (t >= e) return;
    int r = row[t];
    int c = col[t];
    const float4* p = (const float4*)(g_p1 + (size_t)r * HID);
    float4 a = p[0];
    float4 b = p[1];
    float* dst = g_agg1 + (size_t)c * HID;
    red_add_v4(dst,     a);
    red_add_v4(dst + 4, b);
}

// ---------------------------------------------------------------------------
// K4: per-node — h = relu(dinv*(agg1 + p1) + b1); p2 = (h @ W2) * dinv
// ---------------------------------------------------------------------------
__global__ void k_layer1(const float* __restrict__ b1,
                         const float* __restrict__ W2, int n) {
    __shared__ float sW2[HID * NCLS];
    __shared__ float sb1[HID];
    for (int k = threadIdx.x; k < HID * NCLS; k += blockDim.x) sW2[k] = W2[k];
    for (int k = threadIdx.x; k < HID; k += blockDim.x) sb1[k] = b1[k];
    __syncthreads();

    int i = blockIdx.x * blockDim.x + threadIdx.x;
    if (i >= n) return;

    float d = g_dinv[i];
    const float4* ag = (const float4*)(g_agg1 + (size_t)i * HID);
    const float4* pp = (const float4*)(g_p1  + (size_t)i * HID);
    float4 a0 = ag[0], a1 = ag[1];
    float4 p0 = pp[0], p1v = pp[1];
    float h[HID];
    h[0] = d*(a0.x + p0.x);  h[1] = d*(a0.y + p0.y);
    h[2] = d*(a0.z + p0.z);  h[3] = d*(a0.w + p0.w);
    h[4] = d*(a1.x + p1v.x); h[5] = d*(a1.y + p1v.y);
    h[6] = d*(a1.z + p1v.z); h[7] = d*(a1.w + p1v.w);
    #pragma unroll
    for (int j = 0; j < HID; j++) h[j] = fmaxf(h[j] + sb1[j], 0.f);

    float z0 = 0.f, z1 = 0.f;
    #pragma unroll
    for (int j = 0; j < HID; j++) {
        z0 = fmaf(h[j], sW2[j*NCLS + 0], z0);
        z1 = fmaf(h[j], sW2[j*NCLS + 1], z1);
    }
    ((float2*)(g_p2 + (size_t)i * NCLS))[0] = make_float2(z0 * d, z1 * d);
}

// ---------------------------------------------------------------------------
// K5: edge scatter, layer 2 — agg2[col] += p2[row]  (one v2 RED / edge)
// ---------------------------------------------------------------------------
__global__ void k_scatter2(const int* __restrict__ row,
                           const int* __restrict__ col, int e) {
    int t = blockIdx.x * blockDim.x + threadIdx.x;
    if (t >= e) return;
    int r = row[t];
    int c = col[t];
    float2 p = ((const float2*)(g_p2 + (size_t)r * NCLS))[0];
    red_add_v2(g_agg2 + (size_t)c * NCLS, p.x, p.y);
}

// ---------------------------------------------------------------------------
// K6: per-node — o = dinv*(agg2 + p2) + b2; log_softmax over 2 classes
// ---------------------------------------------------------------------------
__global__ void k_out(const float* __restrict__ b2, float* __restrict__ out, int n) {
    int i = blockIdx.x * blockDim.x + threadIdx.x;
    if (i >= n) return;
    float d = g_dinv[i];
    float2 a = ((const float2*)(g_agg2 + (size_t)i * NCLS))[0];
    float2 p = ((const float2*)(g_p2   + (size_t)i * NCLS))[0];
    float o0 = d * (a.x + p.x) + __ldg(b2 + 0);
    float o1 = d * (a.y + p.y) + __ldg(b2 + 1);
    float m  = fmaxf(o0, o1);
    float lse = m + logf(expf(o0 - m) + expf(o1 - m));
    ((float2*)out)[i] = make_float2(o0 - lse, o1 - lse);
}

// ---------------------------------------------------------------------------
extern "C" void kernel_launch(void* const* d_in, const int* in_sizes, int n_in,
                              void* d_out, int out_size) {
    const float* x  = (const float*)d_in[0];
    const float* W1 = (const float*)d_in[1];
    const float* b1 = (const float*)d_in[2];
    const float* W2 = (const float*)d_in[3];
    const float* b2 = (const float*)d_in[4];
    const int*   ei = (const int*)  d_in[5];

    int n = in_sizes[0] / FIN;        // 500000
    int e = in_sizes[5] / 2;          // 8000000
    const int* row = ei;              // edge_index[0]
    const int* col = ei + e;          // edge_index[1]
    float* out = (float*)d_out;

    const int TB = 256;
    int gn = (n + TB - 1) / TB;
    int ge = (e + TB - 1) / TB;

    k_init    <<<gn, TB>>>(n);
    k_degree  <<<ge, TB>>>(col, e);
    k_p1      <<<gn, TB>>>(x, W1, n);
    k_scatter1<<<ge, TB>>>(row, col, e);
    k_layer1  <<<gn, TB>>>(b1, W2, n);
    k_scatter2<<<ge, TB>>>(row, col, e);
    k_out     <<<gn, TB>>>(b2, out, n);
}